// round 5
// baseline (speedup 1.0000x reference)
#include <cuda_runtime.h>
#include <cuda_fp16.h>

#define W0 4096
#define OUTW 1024
#define MAXMIP 8

// Packed half4 texel: rgb + pad, 8 bytes.
struct __align__(8) h4 { __half2 rg; __half2 bz; };

// Mip chain levels 2..8 in fp16 texels. 1,398,016 texels * 8B = ~11.2MB.
// (Level 1 is never materialized: lod<2 pixels compute it on the fly in fp32.)
__device__ h4 g_mh[1398016];

// Texel offset of each level within g_mh (levels 0,1 handled from base).
__constant__ int MIPH_OFF[9] = {
    0,          // level 0 (unused)
    0,          // level 1 (unused)
    0,          // level 2: 1024^2
    1048576,    // level 3:  512^2
    1310720,    // level 4:  256^2
    1376256,    // level 5:  128^2
    1392640,    // level 6:   64^2
    1396736,    // level 7:   32^2
    1397760     // level 8:   16^2
};

__device__ __forceinline__ h4 pack_h4(float r, float g, float b) {
    h4 t;
    t.rg = __floats2half2_rn(r, g);
    t.bz = __floats2half2_rn(b, 0.0f);
    return t;
}

__device__ __forceinline__ float3 unpack_h4(h4 t) {
    float2 rg = __half22float2(t.rg);
    return make_float3(rg.x, rg.y, __low2float(t.bz));
}

__device__ __forceinline__ float3 f3avg(float3 a, float3 b, float3 c, float3 d) {
    return make_float3((a.x + b.x + c.x + d.x) * 0.25f,
                       (a.y + b.y + c.y + d.y) * 0.25f,
                       (a.z + b.z + c.z + d.z) * 0.25f);
}

__device__ __forceinline__ void load12(float* r, const float4* p) {
    float4 f0 = p[0], f1 = p[1], f2 = p[2];
    r[0] = f0.x; r[1]  = f0.y; r[2]  = f0.z; r[3]  = f0.w;
    r[4] = f1.x; r[5]  = f1.y; r[6]  = f1.z; r[7]  = f1.w;
    r[8] = f2.x; r[9]  = f2.y; r[10] = f2.z; r[11] = f2.w;
}

// Kernel A: base (packed fp32 rgb) -> level 2 only.
// One thread = one L2 texel = 4x4 base texels (through fp32 L1 intermediates).
__global__ __launch_bounds__(256) void vt_downA(const float* __restrict__ data) {
    const int w2 = W0 >> 2;              // 1024
    int i = blockIdx.x * blockDim.x + threadIdx.x;
    if (i >= w2 * w2) return;

    int x2 = i & (w2 - 1);
    int y2 = i >> 10;
    const int pitch4 = 3 * w2;           // base row pitch in float4
    const float4* s4 = reinterpret_cast<const float4*>(data)
                       + (size_t)4 * y2 * pitch4 + 3 * x2;

    float a[12], b[12];
    float3 l1[4];

#pragma unroll
    for (int half = 0; half < 2; half++) {
        load12(a, s4 + (2 * half) * pitch4);
        load12(b, s4 + (2 * half + 1) * pitch4);
#pragma unroll
        for (int dx = 0; dx < 2; dx++) {
            l1[2 * half + dx] = make_float3(
                (a[6 * dx + 0] + a[6 * dx + 3] + b[6 * dx + 0] + b[6 * dx + 3]) * 0.25f,
                (a[6 * dx + 1] + a[6 * dx + 4] + b[6 * dx + 1] + b[6 * dx + 4]) * 0.25f,
                (a[6 * dx + 2] + a[6 * dx + 5] + b[6 * dx + 2] + b[6 * dx + 5]) * 0.25f);
        }
    }

    float3 l2 = f3avg(l1[0], l1[1], l1[2], l1[3]);
    g_mh[i] = pack_h4(l2.x, l2.y, l2.z);
}

// Kernel B: level 2 -> levels 3..8 in one kernel.
// Block = 64x64 L2 tile (one L8 texel). Grid: 16x16 blocks of 256 threads.
__global__ __launch_bounds__(256) void vt_downB() {
    __shared__ float4 s4[256];   // L4 tile 16x16
    __shared__ float4 s5[64];    // L5 tile 8x8
    __shared__ float4 s6[16];    // L6 tile 4x4
    __shared__ float4 s7[4];     // L7 tile 2x2

    const h4* __restrict__ L2t = g_mh;
    h4* __restrict__ L3 = g_mh + 1048576;
    h4* __restrict__ L4 = g_mh + 1310720;
    h4* __restrict__ L5 = g_mh + 1376256;
    h4* __restrict__ L6 = g_mh + 1392640;
    h4* __restrict__ L7 = g_mh + 1396736;
    h4* __restrict__ L8 = g_mh + 1397760;

    int t = threadIdx.x;
    int bx = blockIdx.x, by = blockIdx.y;
    int tx = t & 15, ty = t >> 4;

    // Each thread: 4x4 L2 texels at (64bx + 4tx, 64by + 4ty); 2 uint4 loads/row.
    {
        int x0 = 64 * bx + 4 * tx;
        int y0 = 64 * by + 4 * ty;
        const uint4* src = reinterpret_cast<const uint4*>(L2t + (size_t)y0 * 1024 + x0);

        float3 r[4][4];
#pragma unroll
        for (int dy = 0; dy < 4; dy++) {
            uint4 q0 = src[(size_t)dy * 512];
            uint4 q1 = src[(size_t)dy * 512 + 1];
            const __half2* h0 = reinterpret_cast<const __half2*>(&q0);
            const __half2* h1 = reinterpret_cast<const __half2*>(&q1);
            float2 t0rg = __half22float2(h0[0]);
            float2 t1rg = __half22float2(h0[2]);
            float2 t2rg = __half22float2(h1[0]);
            float2 t3rg = __half22float2(h1[2]);
            r[dy][0] = make_float3(t0rg.x, t0rg.y, __low2float(h0[1]));
            r[dy][1] = make_float3(t1rg.x, t1rg.y, __low2float(h0[3]));
            r[dy][2] = make_float3(t2rg.x, t2rg.y, __low2float(h1[1]));
            r[dy][3] = make_float3(t3rg.x, t3rg.y, __low2float(h1[3]));
        }

        float3 l3[4];
#pragma unroll
        for (int dy = 0; dy < 2; dy++)
#pragma unroll
            for (int dx = 0; dx < 2; dx++)
                l3[2 * dy + dx] = f3avg(r[2 * dy][2 * dx], r[2 * dy][2 * dx + 1],
                                        r[2 * dy + 1][2 * dx], r[2 * dy + 1][2 * dx + 1]);

        int x3 = 32 * bx + 2 * tx;
        int y3 = 32 * by + 2 * ty;
        h4* p = L3 + (size_t)y3 * 512 + x3;
        p[0]   = pack_h4(l3[0].x, l3[0].y, l3[0].z);
        p[1]   = pack_h4(l3[1].x, l3[1].y, l3[1].z);
        p[512] = pack_h4(l3[2].x, l3[2].y, l3[2].z);
        p[513] = pack_h4(l3[3].x, l3[3].y, l3[3].z);

        float3 l4 = f3avg(l3[0], l3[1], l3[2], l3[3]);
        L4[(size_t)(16 * by + ty) * 256 + (16 * bx + tx)] = pack_h4(l4.x, l4.y, l4.z);
        s4[ty * 16 + tx] = make_float4(l4.x, l4.y, l4.z, 0.0f);
    }
    __syncthreads();

    if (t < 64) {
        int x = t & 7, y = t >> 3;
        float4 a = s4[(2 * y) * 16 + 2 * x],     b = s4[(2 * y) * 16 + 2 * x + 1];
        float4 c = s4[(2 * y + 1) * 16 + 2 * x], d = s4[(2 * y + 1) * 16 + 2 * x + 1];
        float4 v = make_float4((a.x + b.x + c.x + d.x) * 0.25f,
                               (a.y + b.y + c.y + d.y) * 0.25f,
                               (a.z + b.z + c.z + d.z) * 0.25f, 0.0f);
        L5[(size_t)(8 * by + y) * 128 + (8 * bx + x)] = pack_h4(v.x, v.y, v.z);
        s5[y * 8 + x] = v;
    }
    __syncthreads();

    if (t < 16) {
        int x = t & 3, y = t >> 2;
        float4 a = s5[(2 * y) * 8 + 2 * x],     b = s5[(2 * y) * 8 + 2 * x + 1];
        float4 c = s5[(2 * y + 1) * 8 + 2 * x], d = s5[(2 * y + 1) * 8 + 2 * x + 1];
        float4 v = make_float4((a.x + b.x + c.x + d.x) * 0.25f,
                               (a.y + b.y + c.y + d.y) * 0.25f,
                               (a.z + b.z + c.z + d.z) * 0.25f, 0.0f);
        L6[(size_t)(4 * by + y) * 64 + (4 * bx + x)] = pack_h4(v.x, v.y, v.z);
        s6[y * 4 + x] = v;
    }
    __syncthreads();

    if (t < 4) {
        int x = t & 1, y = t >> 1;
        float4 a = s6[(2 * y) * 4 + 2 * x],     b = s6[(2 * y) * 4 + 2 * x + 1];
        float4 c = s6[(2 * y + 1) * 4 + 2 * x], d = s6[(2 * y + 1) * 4 + 2 * x + 1];
        float4 v = make_float4((a.x + b.x + c.x + d.x) * 0.25f,
                               (a.y + b.y + c.y + d.y) * 0.25f,
                               (a.z + b.z + c.z + d.z) * 0.25f, 0.0f);
        L7[(size_t)(2 * by + y) * 32 + (2 * bx + x)] = pack_h4(v.x, v.y, v.z);
        s7[y * 2 + x] = v;
    }
    __syncthreads();

    if (t == 0) {
        float4 a = s7[0], b = s7[1], c = s7[2], d = s7[3];
        L8[(size_t)by * 16 + bx] = pack_h4((a.x + b.x + c.x + d.x) * 0.25f,
                                           (a.y + b.y + c.y + d.y) * 0.25f,
                                           (a.z + b.z + c.z + d.z) * 0.25f);
    }
}

// wrap helpers
__device__ __forceinline__ void wrap_setup(float u, float v, int w,
                                           int& x0, int& y0, int& x1, int& y1,
                                           float& fx, float& fy) {
    float x = u * (float)w - 0.5f;
    float y = v * (float)w - 0.5f;
    float x0f = floorf(x);
    float y0f = floorf(y);
    fx = x - x0f;
    fy = y - y0f;
    x0 = (int)x0f;
    y0 = (int)y0f;
    if (x0 < 0) x0 += w;
    if (y0 < 0) y0 += w;
    x1 = x0 + 1; if (x1 == w) x1 = 0;
    y1 = y0 + 1; if (y1 == w) y1 = 0;
}

// Bilinear fetch (wrap) from fp16 mip storage (levels >= 2). One 8B load per tap.
__device__ __forceinline__ void vt_bilinear_h(const h4* __restrict__ tex, int w,
                                              float u, float v, float rgb[3]) {
    int x0, y0, x1, y1; float fx, fy;
    wrap_setup(u, v, w, x0, y0, x1, y1, fx, fy);

    float3 p00 = unpack_h4(tex[(size_t)y0 * w + x0]);
    float3 p01 = unpack_h4(tex[(size_t)y0 * w + x1]);
    float3 p10 = unpack_h4(tex[(size_t)y1 * w + x0]);
    float3 p11 = unpack_h4(tex[(size_t)y1 * w + x1]);

    float w00 = (1.0f - fx) * (1.0f - fy);
    float w01 = fx * (1.0f - fy);
    float w10 = (1.0f - fx) * fy;
    float w11 = fx * fy;

    rgb[0] = p00.x * w00 + p01.x * w01 + p10.x * w10 + p11.x * w11;
    rgb[1] = p00.y * w00 + p01.y * w01 + p10.y * w10 + p11.y * w11;
    rgb[2] = p00.z * w00 + p01.z * w01 + p10.z * w10 + p11.z * w11;
}

// Exact fp32 bilinear on the base texture (level 0).
__device__ __forceinline__ void vt_bilinear0(const float* __restrict__ tex,
                                             float u, float v, float rgb[3]) {
    int x0, y0, x1, y1; float fx, fy;
    wrap_setup(u, v, W0, x0, y0, x1, y1, fx, fy);

    const float* p00 = tex + ((size_t)y0 * W0 + x0) * 3;
    const float* p01 = tex + ((size_t)y0 * W0 + x1) * 3;
    const float* p10 = tex + ((size_t)y1 * W0 + x0) * 3;
    const float* p11 = tex + ((size_t)y1 * W0 + x1) * 3;

    float w00 = (1.0f - fx) * (1.0f - fy);
    float w01 = fx * (1.0f - fy);
    float w10 = (1.0f - fx) * fy;
    float w11 = fx * fy;

#pragma unroll
    for (int c = 0; c < 3; c++)
        rgb[c] = p00[c] * w00 + p01[c] * w01 + p10[c] * w10 + p11[c] * w11;
}

// Exact fp32 bilinear at level 1, computing L1 texels on the fly from base.
// L1 texel (lx,ly) = 0.25 * sum of base (2lx..2lx+1, 2ly..2ly+1).
__device__ __forceinline__ void vt_bilinear_l1(const float* __restrict__ tex,
                                               float u, float v, float rgb[3]) {
    const int w1 = W0 >> 1;   // 2048
    int x0, y0, x1, y1; float fx, fy;
    wrap_setup(u, v, w1, x0, y0, x1, y1, fx, fy);

    float w00 = (1.0f - fx) * (1.0f - fy);
    float w01 = fx * (1.0f - fy);
    float w10 = (1.0f - fx) * fy;
    float w11 = fx * fy;

    rgb[0] = rgb[1] = rgb[2] = 0.0f;
    int lx[4] = { x0, x1, x0, x1 };
    int ly[4] = { y0, y0, y1, y1 };
    float lw[4] = { w00, w01, w10, w11 };
#pragma unroll
    for (int k = 0; k < 4; k++) {
        const float* p0 = tex + ((size_t)(2 * ly[k]) * W0 + 2 * lx[k]) * 3;
        const float* p1 = p0 + (size_t)W0 * 3;
#pragma unroll
        for (int c = 0; c < 3; c++)
            rgb[c] += lw[k] * ((p0[c] + p0[3 + c] + p1[c] + p1[3 + c]) * 0.25f);
    }
}

__global__ __launch_bounds__(256) void vt_sample(const float* __restrict__ data,
                          const float2* __restrict__ texc,
                          const float4* __restrict__ deriv,
                          float* __restrict__ out) {
    int i = blockIdx.x * blockDim.x + threadIdx.x;
    if (i >= OUTW * OUTW) return;

    float2 uv = texc[i];
    float4 d = deriv[i];

    float dudx = d.x * (float)W0;
    float dvdx = d.y * (float)W0;
    float dudy = d.z * (float)W0;
    float dvdy = d.w * (float)W0;

    float rho2 = fmaxf(dudx * dudx + dvdx * dvdx, dudy * dudy + dvdy * dvdy);
    float lod = 0.5f * __log2f(fmaxf(rho2, 1e-20f));
    lod = fminf(fmaxf(lod, 0.0f), (float)MAXMIP);

    int l0 = (int)lod;
    if (l0 > MAXMIP) l0 = MAXMIP;
    float frac = lod - (float)l0;
    int l1 = (l0 < MAXMIP) ? (l0 + 1) : MAXMIP;

    float a[3], b[3];
    if (l0 >= 2) {
        // common path (~98.7% of pixels): both levels from stored fp16 mips
        vt_bilinear_h(g_mh + MIPH_OFF[l0], W0 >> l0, uv.x, uv.y, a);
        vt_bilinear_h(g_mh + MIPH_OFF[l1], W0 >> l1, uv.x, uv.y, b);
    } else if (l0 == 1) {
        vt_bilinear_l1(data, uv.x, uv.y, a);
        vt_bilinear_h(g_mh /* level 2 at offset 0 */, W0 >> 2, uv.x, uv.y, b);
    } else {
        vt_bilinear0(data, uv.x, uv.y, a);
        vt_bilinear_l1(data, uv.x, uv.y, b);
    }

    float w0 = 1.0f - frac;
    out[(size_t)3 * i + 0] = a[0] * w0 + b[0] * frac;
    out[(size_t)3 * i + 1] = a[1] * w0 + b[1] * frac;
    out[(size_t)3 * i + 2] = a[2] * w0 + b[2] * frac;
}

extern "C" void kernel_launch(void* const* d_in, const int* in_sizes, int n_in,
                              void* d_out, int out_size) {
    const float* data  = (const float*)d_in[0];   // [1,4096,4096,3]
    const float2* texc = (const float2*)d_in[1];  // [1,1024,1024,2]
    const float4* deriv = (const float4*)d_in[2]; // [1,1024,1024,4]
    float* out = (float*)d_out;                   // [1,1024,1024,3]

    (void)in_sizes; (void)n_in; (void)out_size;

    // A: base -> L2
    vt_downA<<<4096, 256>>>(data);
    // B: L2 -> L3..L8
    {
        dim3 grid(16, 16);
        vt_downB<<<grid, 256>>>();
    }
    // Trilinear sample
    vt_sample<<<4096, 256>>>(data, texc, deriv, out);
}